// round 2
// baseline (speedup 1.0000x reference)
#include <cuda_runtime.h>

// DWT Haar L1 loss, fused single-pass streaming reduction.
// loss = sum_over_2x2_blocks( max(|a+b|,|c+d|) + max(|a-b|,|c-d|) ) / 6291456
// where a,b,c,d are the (pred-target) diffs of the 2x2 block.

#define IMG_ELEMS   262144LL   // 512*512
#define ROW_W       512
#define TOTAL_GROUPS 3145728LL // 96 images * 256 row-pairs * 128 float4-groups
#define NBLOCKS     3072
#define NTHREADS    256
#define INV_COUNT   (1.0 / 6291456.0)

__device__ double g_sum;

__global__ void dwt_init_kernel() {
    g_sum = 0.0;
}

__global__ __launch_bounds__(NTHREADS) void dwt_main_kernel(
    const float* __restrict__ pred, const float* __restrict__ tgt)
{
    float acc = 0.0f;
    const long long stride = (long long)gridDim.x * blockDim.x;
    for (long long i = (long long)blockIdx.x * blockDim.x + threadIdx.x;
         i < TOTAL_GROUPS; i += stride)
    {
        // i -> (img, row-pair r, col-group g): 256*128 = 32768 groups per image
        long long img = i >> 15;
        int rem = (int)(i & 32767);
        int r   = rem >> 7;        // 0..255
        int g   = rem & 127;       // 0..127
        long long base = img * IMG_ELEMS + (long long)(2 * r) * ROW_W + (long long)g * 4;

        float4 p0 = *reinterpret_cast<const float4*>(pred + base);
        float4 p1 = *reinterpret_cast<const float4*>(pred + base + ROW_W);
        float4 t0 = *reinterpret_cast<const float4*>(tgt  + base);
        float4 t1 = *reinterpret_cast<const float4*>(tgt  + base + ROW_W);

        // diffs: top row (a,b) pairs, bottom row (c,d) pairs — two 2x2 blocks
        float a0 = p0.x - t0.x, b0 = p0.y - t0.y;
        float c0 = p1.x - t1.x, d0 = p1.y - t1.y;
        float a1 = p0.z - t0.z, b1 = p0.w - t0.w;
        float c1 = p1.z - t1.z, d1 = p1.w - t1.w;

        // block contribution: max(|a+b|,|c+d|) + max(|a-b|,|c-d|)
        acc += fmaxf(fabsf(a0 + b0), fabsf(c0 + d0))
             + fmaxf(fabsf(a0 - b0), fabsf(c0 - d0));
        acc += fmaxf(fabsf(a1 + b1), fabsf(c1 + d1))
             + fmaxf(fabsf(a1 - b1), fabsf(c1 - d1));
    }

    // warp reduce
    #pragma unroll
    for (int off = 16; off > 0; off >>= 1)
        acc += __shfl_down_sync(0xFFFFFFFFu, acc, off);

    __shared__ float warp_sums[NTHREADS / 32];
    int lane = threadIdx.x & 31;
    int wid  = threadIdx.x >> 5;
    if (lane == 0) warp_sums[wid] = acc;
    __syncthreads();

    if (wid == 0) {
        float v = (lane < NTHREADS / 32) ? warp_sums[lane] : 0.0f;
        #pragma unroll
        for (int off = 4; off > 0; off >>= 1)
            v += __shfl_down_sync(0xFFFFFFFFu, v, off);
        if (lane == 0)
            atomicAdd(&g_sum, (double)v);
    }
}

__global__ void dwt_final_kernel(float* __restrict__ out) {
    out[0] = (float)(g_sum * INV_COUNT);
}

extern "C" void kernel_launch(void* const* d_in, const int* in_sizes, int n_in,
                              void* d_out, int out_size) {
    const float* pred = (const float*)d_in[0];
    const float* tgt  = (const float*)d_in[1];
    float* out = (float*)d_out;

    dwt_init_kernel<<<1, 1>>>();
    dwt_main_kernel<<<NBLOCKS, NTHREADS>>>(pred, tgt);
    dwt_final_kernel<<<1, 1>>>(out);
}